// round 14
// baseline (speedup 1.0000x reference)
#include <cuda_runtime.h>
#include <cuda_bf16.h>
#include <cstdint>
#include <math.h>

// Problem shape (fixed)
#define NB  4
#define NS  2048
#define ND  1024
#define NH  16
#define NHD 64
#define NM  (NB * NS)   // 8192 rows
#define A8M ((size_t)NM * ND)    // 8388608
#define W1M ((size_t)ND * ND)    // 1048576

// ---- Scratch (device globals: allocation-free) ----
__device__ __nv_bfloat16 g_Ah[3 * A8M];
__device__ __nv_bfloat16 g_Al[3 * A8M];
__device__ __nv_bfloat16 g_Wph[4 * W1M];
__device__ __nv_bfloat16 g_Wpl[4 * W1M];
__device__ __nv_bfloat16 g_Qh[A8M];
__device__ __nv_bfloat16 g_Ql[A8M];
__device__ __nv_bfloat16 g_Kh[A8M];
__device__ __nv_bfloat16 g_Kl[A8M];
__device__ __nv_bfloat16 g_Vh[A8M];
__device__ __nv_bfloat16 g_Vl[A8M];
__device__ __nv_bfloat16 g_Mh[A8M];
__device__ __nv_bfloat16 g_Ml[A8M];

// ============================ PTX helpers ====================================
__device__ __forceinline__ uint32_t smem_u32(const void* p) {
    uint32_t a;
    asm("{ .reg .u64 t; cvta.to.shared.u64 t, %1; cvt.u32.u64 %0, t; }"
        : "=r"(a) : "l"(p));
    return a;
}
__device__ __forceinline__ float ex2f(float x) {
    float y;
    asm("ex2.approx.ftz.f32 %0, %1;" : "=f"(y) : "f"(x));
    return y;
}

#define LDSM4(R0, R1, R2, R3, ADDR) \
    asm volatile("ldmatrix.sync.aligned.m8n8.x4.shared.b16 {%0,%1,%2,%3}, [%4];" \
                 : "=r"(R0), "=r"(R1), "=r"(R2), "=r"(R3) : "r"(ADDR))
#define LDSM4T(R0, R1, R2, R3, ADDR) \
    asm volatile("ldmatrix.sync.aligned.m8n8.x4.trans.shared.b16 {%0,%1,%2,%3}, [%4];" \
                 : "=r"(R0), "=r"(R1), "=r"(R2), "=r"(R3) : "r"(ADDR))

#define MMA_BF16(C, A, B0, B1) \
    asm volatile("mma.sync.aligned.m16n8k16.row.col.f32.bf16.bf16.f32 " \
                 "{%0,%1,%2,%3}, {%4,%5,%6,%7}, {%8,%9}, {%0,%1,%2,%3};" \
                 : "+f"((C)[0]), "+f"((C)[1]), "+f"((C)[2]), "+f"((C)[3]) \
                 : "r"((A)[0]), "r"((A)[1]), "r"((A)[2]), "r"((A)[3]), \
                   "r"(B0), "r"(B1))

#define CP_A16(DST, SRC) \
    asm volatile("cp.async.cg.shared.global [%0], [%1], 16;" \
                 :: "r"(DST), "l"(SRC) : "memory")
#define CP_COMMIT() asm volatile("cp.async.commit_group;" ::: "memory")
#define CP_WAIT0()  asm volatile("cp.async.wait_group 0;" ::: "memory")
#define CP_WAIT1()  asm volatile("cp.async.wait_group 1;" ::: "memory")

__device__ __forceinline__ void bsplit4(float4 v, uint2& hi, uint2& lo) {
    __nv_bfloat16 h0 = __float2bfloat16(v.x);
    __nv_bfloat16 h1 = __float2bfloat16(v.y);
    __nv_bfloat16 h2 = __float2bfloat16(v.z);
    __nv_bfloat16 h3 = __float2bfloat16(v.w);
    __nv_bfloat16 l0 = __float2bfloat16(v.x - __bfloat162float(h0));
    __nv_bfloat16 l1 = __float2bfloat16(v.y - __bfloat162float(h1));
    __nv_bfloat16 l2 = __float2bfloat16(v.z - __bfloat162float(h2));
    __nv_bfloat16 l3 = __float2bfloat16(v.w - __bfloat162float(h3));
    hi.x = ((uint32_t)__bfloat16_as_ushort(h1) << 16) | __bfloat16_as_ushort(h0);
    hi.y = ((uint32_t)__bfloat16_as_ushort(h3) << 16) | __bfloat16_as_ushort(h2);
    lo.x = ((uint32_t)__bfloat16_as_ushort(l1) << 16) | __bfloat16_as_ushort(l0);
    lo.y = ((uint32_t)__bfloat16_as_ushort(l3) << 16) | __bfloat16_as_ushort(l2);
}
__device__ __forceinline__ void psplit2(float a, float b, uint32_t& hi, uint32_t& lo) {
    __nv_bfloat16 ha = __float2bfloat16(a), hb = __float2bfloat16(b);
    __nv_bfloat16 la = __float2bfloat16(a - __bfloat162float(ha));
    __nv_bfloat16 lb = __float2bfloat16(b - __bfloat162float(hb));
    hi = ((uint32_t)__bfloat16_as_ushort(hb) << 16) | __bfloat16_as_ushort(ha);
    lo = ((uint32_t)__bfloat16_as_ushort(lb) << 16) | __bfloat16_as_ushort(la);
}

#define QSCALE 0.18033688011112042f

// ============================================================================
// Fused splitters
// ============================================================================
__global__ void split_inputs(const float* __restrict__ q,
                             const float* __restrict__ k,
                             const float* __restrict__ v)
{
    const size_t n4 = A8M >> 2;
    size_t i = (size_t)blockIdx.x * blockDim.x + threadIdx.x;
    int plane = (int)(i / n4);
    size_t j = i - (size_t)plane * n4;
    const float* src = (plane == 0) ? q : (plane == 1) ? k : v;
    float4 vv = ((const float4*)src)[j];
    uint2 hi, lo;
    bsplit4(vv, hi, lo);
    ((uint2*)g_Ah)[i] = hi;
    ((uint2*)g_Al)[i] = lo;
}
__global__ void split_weights(const float* __restrict__ w0,
                              const float* __restrict__ w1,
                              const float* __restrict__ w2,
                              const float* __restrict__ w3)
{
    const size_t n4 = W1M >> 2;
    size_t i = (size_t)blockIdx.x * blockDim.x + threadIdx.x;
    int plane = (int)(i / n4);
    size_t j = i - (size_t)plane * n4;
    const float* src = (plane == 0) ? w0 : (plane == 1) ? w1 : (plane == 2) ? w2 : w3;
    float4 vv = ((const float4*)src)[j];
    uint2 hi, lo;
    bsplit4(vv, hi, lo);
    ((uint2*)g_Wph)[i] = hi;
    ((uint2*)g_Wpl)[i] = lo;
}

// Stage layout (GEMM): rows of 32 bf16 (64B) + 16B pad.
#define ROWB   80
#define TILEB  (128 * ROWB)
#define OFF_AHI 0
#define OFF_ALO (TILEB)
#define OFF_WHI (2 * TILEB)
#define OFF_WLO (3 * TILEB)
#define STAGEB  (4 * TILEB)
#define GSMEM_TOTAL (2 * STAGEB)  // 81920

// ============================================================================
// Shared GEMM body (unchanged from measured 166.8us version).
// ============================================================================
__device__ __forceinline__ void gemm_body(
    const __nv_bfloat16* __restrict__ Ah, const __nv_bfloat16* __restrict__ Al,
    const __nv_bfloat16* __restrict__ Wh, const __nv_bfloat16* __restrict__ Wl,
    const float* __restrict__ bias, float* __restrict__ Cext,
    int dstsel, char* dsm)
{
    const uint32_t sbase = smem_u32(dsm);
    __shared__ float s_bias[128];

    const int t    = threadIdx.x;
    const int wid  = t >> 5;
    const int lane = t & 31;
    const int m0 = blockIdx.y * 128;
    const int n0 = blockIdx.x * 128;
    const int wm0 = (wid >> 2) * 64;
    const int wn0 = (wid & 3) * 32;

    if (t < 32) ((float4*)s_bias)[t] = *(const float4*)&bias[n0 + t * 4];

    const uint32_t offA = (uint32_t)(wm0 + (lane & 15)) * ROWB
                        + (uint32_t)((lane >> 4) * 8) * 2;
    const uint32_t offB = (uint32_t)(wn0 + ((lane >> 4) & 1) * 8 + (lane & 7)) * ROWB
                        + (uint32_t)(((lane >> 3) & 1) * 8) * 2;

    float acc[4][4][4];
    #pragma unroll
    for (int i = 0; i < 4; i++)
        #pragma unroll
        for (int j = 0; j < 4; j++)
            #pragma unroll
            for (int r = 0; r < 4; r++) acc[i][j][r] = 0.0f;

    auto stage = [&](int c, int bufsel) {
        const int k0 = c * 32;
        const uint32_t dstb = sbase + (uint32_t)bufsel * STAGEB;
        #pragma unroll
        for (int i = 0; i < 8; i++) {
            int f   = i * 256 + t;
            int p   = f >> 9;
            int cc  = f & 511;
            int row = cc >> 2;
            int qq  = cc & 3;
            uint32_t dst = dstb + (uint32_t)p * TILEB + (uint32_t)row * ROWB + (uint32_t)qq * 16;
            const __nv_bfloat16* src;
            if (p == 0)      src = Ah + (size_t)(m0 + row) * ND + k0 + qq * 8;
            else if (p == 1) src = Al + (size_t)(m0 + row) * ND + k0 + qq * 8;
            else if (p == 2) src = Wh + (size_t)(n0 + row) * ND + k0 + qq * 8;
            else             src = Wl + (size_t)(n0 + row) * ND + k0 + qq * 8;
            CP_A16(dst, src);
        }
        CP_COMMIT();
    };

    stage(0, 0);
    stage(1, 1);

    for (int c = 0; c < 32; c++) {
        if (c < 31) { CP_WAIT1(); } else { CP_WAIT0(); }
        __syncthreads();
        const uint32_t sb = sbase + (uint32_t)(c & 1) * STAGEB;

        #pragma unroll
        for (int ks = 0; ks < 2; ks++) {
            const uint32_t ka = (uint32_t)ks * 32;
            uint32_t ah[16];
            uint32_t bb[8];

            #pragma unroll
            for (int mi = 0; mi < 4; mi++)
                LDSM4(ah[mi*4+0], ah[mi*4+1], ah[mi*4+2], ah[mi*4+3],
                      sb + OFF_AHI + offA + ka + (uint32_t)mi * (16 * ROWB));
            #pragma unroll
            for (int nj = 0; nj < 2; nj++)
                LDSM4(bb[nj*4+0], bb[nj*4+1], bb[nj*4+2], bb[nj*4+3],
                      sb + OFF_WHI + offB + ka + (uint32_t)nj * (16 * ROWB));
            #pragma unroll
            for (int mi = 0; mi < 4; mi++)
                #pragma unroll
                for (int ni = 0; ni < 4; ni++)
                    MMA_BF16(acc[mi][ni], &ah[mi*4],
                             bb[(ni >> 1) * 4 + (ni & 1) * 2],
                             bb[(ni >> 1) * 4 + (ni & 1) * 2 + 1]);
            #pragma unroll
            for (int nj = 0; nj < 2; nj++)
                LDSM4(bb[nj*4+0], bb[nj*4+1], bb[nj*4+2], bb[nj*4+3],
                      sb + OFF_WLO + offB + ka + (uint32_t)nj * (16 * ROWB));
            #pragma unroll
            for (int mi = 0; mi < 4; mi++)
                #pragma unroll
                for (int ni = 0; ni < 4; ni++)
                    MMA_BF16(acc[mi][ni], &ah[mi*4],
                             bb[(ni >> 1) * 4 + (ni & 1) * 2],
                             bb[(ni >> 1) * 4 + (ni & 1) * 2 + 1]);
            #pragma unroll
            for (int mi = 0; mi < 4; mi++)
                LDSM4(ah[mi*4+0], ah[mi*4+1], ah[mi*4+2], ah[mi*4+3],
                      sb + OFF_ALO + offA + ka + (uint32_t)mi * (16 * ROWB));
            #pragma unroll
            for (int nj = 0; nj < 2; nj++)
                LDSM4(bb[nj*4+0], bb[nj*4+1], bb[nj*4+2], bb[nj*4+3],
                      sb + OFF_WHI + offB + ka + (uint32_t)nj * (16 * ROWB));
            #pragma unroll
            for (int mi = 0; mi < 4; mi++)
                #pragma unroll
                for (int ni = 0; ni < 4; ni++)
                    MMA_BF16(acc[mi][ni], &ah[mi*4],
                             bb[(ni >> 1) * 4 + (ni & 1) * 2],
                             bb[(ni >> 1) * 4 + (ni & 1) * 2 + 1]);
        }
        __syncthreads();
        if (c + 2 < 32) stage(c + 2, c & 1);
    }

    // ---- epilogue ----
    const int cr = lane >> 2;
    const int cc2 = (lane & 3) * 2;
    if (dstsel < 3) {
        const float qs = (dstsel == 0) ? QSCALE : 1.0f;
        __nv_bfloat16* Ph = (dstsel == 0) ? g_Qh : (dstsel == 1) ? g_Kh : g_Vh;
        __nv_bfloat16* Pl = (dstsel == 0) ? g_Ql : (dstsel == 1) ? g_Kl : g_Vl;
        #pragma unroll
        for (int mi = 0; mi < 4; mi++) {
            const int r0 = m0 + wm0 + mi * 16 + cr;
            #pragma unroll
            for (int ni = 0; ni < 4; ni++) {
                const int col = wn0 + ni * 8 + cc2;
                const float b0 = s_bias[col];
                const float b1 = s_bias[col + 1];
                float v0 = (acc[mi][ni][0] + b0) * qs;
                float v1 = (acc[mi][ni][1] + b1) * qs;
                float v2 = (acc[mi][ni][2] + b0) * qs;
                float v3 = (acc[mi][ni][3] + b1) * qs;
                uint32_t hi, lo;
                psplit2(v0, v1, hi, lo);
                *(uint32_t*)&Ph[(size_t)r0 * ND + n0 + col] = hi;
                *(uint32_t*)&Pl[(size_t)r0 * ND + n0 + col] = lo;
                psplit2(v2, v3, hi, lo);
                *(uint32_t*)&Ph[(size_t)(r0 + 8) * ND + n0 + col] = hi;
                *(uint32_t*)&Pl[(size_t)(r0 + 8) * ND + n0 + col] = lo;
            }
        }
    } else {
        #pragma unroll
        for (int mi = 0; mi < 4; mi++) {
            const int r0 = m0 + wm0 + mi * 16 + cr;
            #pragma unroll
            for (int ni = 0; ni < 4; ni++) {
                const int col = wn0 + ni * 8 + cc2;
                const float b0 = s_bias[col];
                const float b1 = s_bias[col + 1];
                float2 o0, o1;
                o0.x = acc[mi][ni][0] + b0;
                o0.y = acc[mi][ni][1] + b1;
                o1.x = acc[mi][ni][2] + b0;
                o1.y = acc[mi][ni][3] + b1;
                *(float2*)&Cext[(size_t)r0 * ND + n0 + col] = o0;
                *(float2*)&Cext[(size_t)(r0 + 8) * ND + n0 + col] = o1;
            }
        }
    }
}

__global__ __launch_bounds__(256, 2) void gemm_qkv(
    const float* __restrict__ bq, const float* __restrict__ bk,
    const float* __restrict__ bv)
{
    extern __shared__ char dsm[];
    const int z = blockIdx.z;
    const __nv_bfloat16* Ah = g_Ah + (size_t)z * A8M;
    const __nv_bfloat16* Al = g_Al + (size_t)z * A8M;
    const __nv_bfloat16* Wh = g_Wph + (size_t)z * W1M;
    const __nv_bfloat16* Wl = g_Wpl + (size_t)z * W1M;
    const float* bias = (z == 0) ? bq : (z == 1) ? bk : bv;
    gemm_body(Ah, Al, Wh, Wl, bias, nullptr, z, dsm);
}

__global__ __launch_bounds__(256, 2) void gemm_o(
    const float* __restrict__ bias, float* __restrict__ out)
{
    extern __shared__ char dsm[];
    gemm_body(g_Mh, g_Ml, g_Wph + 3 * W1M, g_Wpl + 3 * W1M, bias, out, 3, dsm);
}

// ============================================================================
// Tensor-core flash attention: half-tile softmax pipelining.
// K: 2 buffers, V: 3 buffers (lifetime spans 2 iterations).
// smem/CTA = 5 * 18432 = 92160 -> 2 CTAs/SM.
// Grid (B*NH, NS/128), 256 threads (8 warps x 16 Q rows).
// ============================================================================
#define AROWB 144           // 64 bf16 (128B) + 16B pad
#define PLB   9216          // one plane: 64 rows x 144B
#define BUFB  (2 * PLB)     // hi+lo planes = 18432
#define ASMEM_TOTAL (5 * BUFB)   // 92160

__global__ __launch_bounds__(256, 2) void attn_tc(float* __restrict__ ctx_out)
{
    extern __shared__ char sm[];
    const uint32_t sb = smem_u32(sm);
    const int t = threadIdx.x, wid = t >> 5, lane = t & 31;
    const int b = blockIdx.x >> 4, h = blockIdx.x & 15;
    const int q0 = blockIdx.y * 128;

    // K buffers at sb + {0,1}*BUFB ; V buffers at sb + 2*BUFB + {0,1,2}*BUFB
    const uint32_t vbase = sb + 2u * BUFB;

    // ---- stage Q (transient, into K-buffer region [0, 36864)) ----
    #pragma unroll
    for (int i = 0; i < 8; i++) {
        int f   = i * 256 + t;
        int p   = f >> 10;
        int cc  = f & 1023;
        int row = cc >> 3;
        int qq  = cc & 7;
        uint32_t dst = sb + (uint32_t)p * (2 * PLB) + (uint32_t)row * AROWB + (uint32_t)qq * 16;
        const __nv_bfloat16* src = ((p == 0) ? g_Qh : g_Ql)
                                 + ((size_t)b * NS + q0 + row) * ND + h * 64 + qq * 8;
        CP_A16(dst, src);
    }
    CP_COMMIT();
    CP_WAIT0();
    __syncthreads();

    uint32_t qh[4][4], ql[4][4];
    const uint32_t offA = (uint32_t)(wid * 16 + (lane & 15)) * AROWB
                        + (uint32_t)((lane >> 4) * 8) * 2;
    #pragma unroll
    for (int ks = 0; ks < 4; ks++) {
        LDSM4(qh[ks][0], qh[ks][1], qh[ks][2], qh[ks][3], sb + offA + ks * 32);
        LDSM4(ql[ks][0], ql[ks][1], ql[ks][2], ql[ks][3], sb + 2 * PLB + offA + ks * 32);
    }
    __syncthreads();   // Q frags in regs; K region reusable

    auto stage_k = [&](int kt, int bufsel) {
        const uint32_t dstb = sb + (uint32_t)bufsel * BUFB;
        #pragma unroll
        for (int i = 0; i < 4; i++) {
            int f   = i * 256 + t;      // 0..1023
            int p   = f >> 9;           // 0: hi, 1: lo
            int cc  = f & 511;
            int row = cc >> 3;
            int qq  = cc & 7;
            uint32_t dst = dstb + (uint32_t)p * PLB + (uint32_t)row * AROWB + (uint32_t)qq * 16;
            const __nv_bfloat16* src = ((p == 0) ? g_Kh : g_Kl)
                + ((size_t)b * NS + kt * 64 + row) * ND + h * 64 + qq * 8;
            CP_A16(dst, src);
        }
    };
    auto stage_v = [&](int kt, int bufsel) {
        const uint32_t dstb = vbase + (uint32_t)bufsel * BUFB;
        #pragma unroll
        for (int i = 0; i < 4; i++) {
            int f   = i * 256 + t;
            int p   = f >> 9;
            int cc  = f & 511;
            int row = cc >> 3;
            int qq  = cc & 7;
            uint32_t dst = dstb + (uint32_t)p * PLB + (uint32_t)row * AROWB + (uint32_t)qq * 16;
            const __nv_bfloat16* src = ((p == 0) ? g_Vh : g_Vl)
                + ((size_t)b * NS + kt * 64 + row) * ND + h * 64 + qq * 8;
            CP_A16(dst, src);
        }
    };

    // Prologue: K0,K1,V0,V1 in one group.
    stage_k(0, 0); stage_k(1, 1);
    stage_v(0, 0); stage_v(1, 1);
    CP_COMMIT();
    CP_WAIT0();
    __syncthreads();

    float ctx[8][4];
    #pragma unroll
    for (int i = 0; i < 8; i++)
        #pragma unroll
        for (int j = 0; j < 4; j++) ctx[i][j] = 0.0f;
    float m0 = -1e30f, m1 = -1e30f, l0 = 0.0f, l1 = 0.0f;
    float s_a[4][4], s_b[4][4];
    uint32_t pah[2][4], pal[2][4];

    const uint32_t offBs = (uint32_t)(((lane >> 4) & 1) * 8 + (lane & 7)) * AROWB
                         + (uint32_t)(((lane >> 3) & 1) * 8) * 2;
    const uint32_t offBt = (uint32_t)(lane & 15) * AROWB + (uint32_t)((lane >> 4) * 8) * 2;

    // QK on one 32-key half (nbp0 = 0 or 2) into sh[4][4]
    auto qk_half = [&](uint32_t kbuf, int nbp0, float (*sh)[4]) {
        #pragma unroll
        for (int i = 0; i < 4; i++)
            #pragma unroll
            for (int j = 0; j < 4; j++) sh[i][j] = 0.0f;
        #pragma unroll
        for (int ks = 0; ks < 4; ks++) {
            #pragma unroll
            for (int nb = 0; nb < 2; nb++) {
                const int nbp = nbp0 + nb;
                uint32_t kh[4], kl[4];
                uint32_t a = kbuf + (uint32_t)nbp * (16 * AROWB) + (uint32_t)ks * 32 + offBs;
                LDSM4(kh[0], kh[1], kh[2], kh[3], a);
                LDSM4(kl[0], kl[1], kl[2], kl[3], a + PLB);
                MMA_BF16(sh[2*nb],   qh[ks], kh[0], kh[1]);
                MMA_BF16(sh[2*nb+1], qh[ks], kh[2], kh[3]);
                MMA_BF16(sh[2*nb],   qh[ks], kl[0], kl[1]);
                MMA_BF16(sh[2*nb+1], qh[ks], kl[2], kl[3]);
                MMA_BF16(sh[2*nb],   ql[ks], kh[0], kh[1]);
                MMA_BF16(sh[2*nb+1], ql[ks], kh[2], kh[3]);
            }
        }
    };

    // Online-softmax on one 32-key half; emits P frags into pah/pal.
    auto softmax_half = [&](float (*sh)[4]) {
        float mn0 = sh[0][0], mn1 = sh[0][2];
        #pragma unroll
        for (int nb = 0; nb < 4; nb++) {
            mn0 = fmaxf(mn0, fmaxf(sh[nb][0], sh[nb][1]));
            mn1 = fmaxf(mn1, fmaxf(sh[nb][2], sh[nb][3]));
        }
        mn0 = fmaxf(mn0, __shfl_xor_sync(0xffffffffu, mn0, 1));
        mn0 = fmaxf(mn0, __shfl_xor_sync(0xffffffffu, mn0, 2));
        mn1 = fmaxf(mn1, __shfl_xor_sync(0xffffffffu, mn1, 1));
        mn1 = fmaxf(mn1, __shfl_xor_sync(0xffffffffu, mn1, 2));
        float nm0 = fmaxf(m0, mn0), nm1 = fmaxf(m1, mn1);
        float c0 = ex2f(m0 - nm0), c1 = ex2f(m1 - nm1);
        m0 = nm0; m1 = nm1;

        float sum0 = 0.0f, sum1 = 0.0f;
        #pragma unroll
        for (int nb = 0; nb < 4; nb++) {
            sh[nb][0] = ex2f(sh[nb][0] - m0);
            sh[nb][1] = ex2f(sh[nb][1] - m0);
            sh[nb][2] = ex2f(sh[nb][2] - m1);
            sh[nb][3] = ex2f(sh[nb][3] - m1);
            sum0 += sh[nb][0] + sh[nb][1];
            sum1 += sh[nb][2] + sh[nb][3];
        }
        sum0 += __shfl_xor_sync(0xffffffffu, sum0, 1);
        sum0 += __shfl_xor_sync(0xffffffffu, sum0, 2);
        sum1 += __shfl_xor_sync(0xffffffffu, sum1, 1);
        sum1 += __shfl_xor_sync(0xffffffffu, sum1, 2);
        l0 = l0 * c0 + sum0;
        l1 = l1 * c1 + sum1;
        #pragma unroll
        for (int db = 0; db < 8; db++) {
            ctx[db][0] *= c0; ctx[db][1] *= c0;
            ctx[db][2] *= c1; ctx[db][3] *= c1;
        }
        #pragma unroll
        for (int ks2 = 0; ks2 < 2; ks2++) {
            const int e = 2 * ks2, o = 2 * ks2 + 1;
            psplit2(sh[e][0], sh[e][1], pah[ks2][0], pal[ks2][0]);
            psplit2(sh[e][2], sh[e][3], pah[ks2][1], pal[ks2][1]);
            psplit2(sh[o][0], sh[o][1], pah[ks2][2], pal[ks2][2]);
            psplit2(sh[o][2], sh[o][3], pah[ks2][3], pal[ks2][3]);
        }
    };

    // PV on one 32-key half (V row chunks ksBase, ksBase+1)
    auto pv_half = [&](uint32_t vbuf, int ksBase) {
        #pragma unroll
        for (int ks2 = 0; ks2 < 2; ks2++) {
            #pragma unroll
            for (int dbp = 0; dbp < 4; dbp++) {
                uint32_t vh[4], vl[4];
                uint32_t a = vbuf + (uint32_t)(ksBase + ks2) * (16 * AROWB)
                           + (uint32_t)dbp * 32 + offBt;
                LDSM4T(vh[0], vh[1], vh[2], vh[3], a);
                LDSM4T(vl[0], vl[1], vl[2], vl[3], a + PLB);
                MMA_BF16(ctx[2*dbp],   pah[ks2], vh[0], vh[1]);
                MMA_BF16(ctx[2*dbp+1], pah[ks2], vh[2], vh[3]);
                MMA_BF16(ctx[2*dbp],   pah[ks2], vl[0], vl[1]);
                MMA_BF16(ctx[2*dbp+1], pah[ks2], vl[2], vl[3]);
                MMA_BF16(ctx[2*dbp],   pal[ks2], vh[0], vh[1]);
                MMA_BF16(ctx[2*dbp+1], pal[ks2], vh[2], vh[3]);
            }
        }
    };

    const int NT = NS / 64;   // 32 tiles
    for (int kt = 0; kt <= NT; kt++) {
        const uint32_t kb = sb + (uint32_t)(kt & 1) * BUFB;
        if (kt < NT)
            qk_half(kb, 0, s_a);                    // tensor: 48 MMA
        if (kt >= 1) {
            softmax_half(s_b);                      // overlaps QK_a drain
            pv_half(vbase + (uint32_t)((kt - 1) % 3) * BUFB, 2);
        }
        if (kt < NT) {
            qk_half(kb, 2, s_b);                    // tensor: 48 MMA
            softmax_half(s_a);                      // overlaps QK_b drain
            pv_half(vbase + (uint32_t)(kt % 3) * BUFB, 0);
        }
        __syncthreads();
        if (kt < NT) {
            int kk = (kt + 2 > NT - 1) ? NT - 1 : kt + 2;
            stage_k(kk, kt & 1);
            stage_v(kk, (kt + 2) % 3);
            CP_COMMIT();
            CP_WAIT1();
        } else {
            CP_WAIT0();
        }
        __syncthreads();
    }

    // ---- epilogue: ctx (fp32) + merged split planes ----
    const float i0 = 1.0f / l0, i1 = 1.0f / l1;
    const int r0 = q0 + wid * 16 + (lane >> 2);
    #pragma unroll
    for (int db = 0; db < 8; db++) {
        const int col = db * 8 + (lane & 3) * 2;
        float2 o0, o1;
        o0.x = ctx[db][0] * i0; o0.y = ctx[db][1] * i0;
        o1.x = ctx[db][2] * i1; o1.y = ctx[db][3] * i1;
        *(float2*)&ctx_out[(((size_t)b * NH + h) * NS + r0) * NHD + col]     = o0;
        *(float2*)&ctx_out[(((size_t)b * NH + h) * NS + r0 + 8) * NHD + col] = o1;
        uint32_t hi, lo;
        psplit2(o0.x, o0.y, hi, lo);
        *(uint32_t*)&g_Mh[((size_t)b * NS + r0) * ND + h * NHD + col] = hi;
        *(uint32_t*)&g_Ml[((size_t)b * NS + r0) * ND + h * NHD + col] = lo;
        psplit2(o1.x, o1.y, hi, lo);
        *(uint32_t*)&g_Mh[((size_t)b * NS + r0 + 8) * ND + h * NHD + col] = hi;
        *(uint32_t*)&g_Ml[((size_t)b * NS + r0 + 8) * ND + h * NHD + col] = lo;
    }
}

// ----------------------------------------------------------------------------
extern "C" void kernel_launch(void* const* d_in, const int* in_sizes, int n_in,
                              void* d_out, int out_size)
{
    (void)in_sizes; (void)n_in; (void)out_size;
    const float* q    = (const float*)d_in[0];
    const float* k    = (const float*)d_in[1];
    const float* v    = (const float*)d_in[2];
    const float* wq_w = (const float*)d_in[3];
    const float* wq_b = (const float*)d_in[4];
    const float* wk_w = (const float*)d_in[5];
    const float* wk_b = (const float*)d_in[6];
    const float* wv_w = (const float*)d_in[7];
    const float* wv_b = (const float*)d_in[8];
    const float* wo_w = (const float*)d_in[9];
    const float* wo_b = (const float*)d_in[10];

    float* out = (float*)d_out;                    // [B,S,D]
    float* ctx = out + (size_t)NM * ND;            // [B,H,S,HD]

    cudaFuncSetAttribute(gemm_qkv, cudaFuncAttributeMaxDynamicSharedMemorySize,
                         GSMEM_TOTAL);
    cudaFuncSetAttribute(gemm_o, cudaFuncAttributeMaxDynamicSharedMemorySize,
                         GSMEM_TOTAL);
    cudaFuncSetAttribute(attn_tc, cudaFuncAttributeMaxDynamicSharedMemorySize,
                         ASMEM_TOTAL);

    split_inputs<<<(unsigned)(3 * (A8M >> 2) / 256), 256>>>(q, k, v);
    split_weights<<<(unsigned)(4 * (W1M >> 2) / 256), 256>>>(wq_w, wk_w, wv_w, wo_w);

    dim3 gqkv(ND / 128, NM / 128, 3);              // (8, 64, 3)
    gemm_qkv<<<gqkv, 256, GSMEM_TOTAL>>>(wq_b, wk_b, wv_b);   // -> Q/K/V planes

    attn_tc<<<dim3(NB * NH, NS / 128), 256, ASMEM_TOTAL>>>(ctx); // -> ctx + merged

    dim3 go(ND / 128, NM / 128);                   // (8, 64)
    gemm_o<<<go, 256, GSMEM_TOTAL>>>(wo_b, out);   // -> out
}

// round 15
// speedup vs baseline: 1.0375x; 1.0375x over previous
#include <cuda_runtime.h>
#include <cuda_bf16.h>
#include <cstdint>
#include <math.h>

// Problem shape (fixed)
#define NB  4
#define NS  2048
#define ND  1024
#define NH  16
#define NHD 64
#define NM  (NB * NS)   // 8192 rows
#define A8M ((size_t)NM * ND)    // 8388608
#define W1M ((size_t)ND * ND)    // 1048576

// ---- Scratch (device globals: allocation-free) ----
__device__ __nv_bfloat16 g_Ah[3 * A8M];
__device__ __nv_bfloat16 g_Al[3 * A8M];
__device__ __nv_bfloat16 g_Wph[4 * W1M];
__device__ __nv_bfloat16 g_Wpl[4 * W1M];
__device__ __nv_bfloat16 g_Qh[A8M];
__device__ __nv_bfloat16 g_Ql[A8M];
__device__ __nv_bfloat16 g_Kh[A8M];
__device__ __nv_bfloat16 g_Kl[A8M];
__device__ __nv_bfloat16 g_Vh[A8M];
__device__ __nv_bfloat16 g_Vl[A8M];
__device__ __nv_bfloat16 g_Mh[A8M];
__device__ __nv_bfloat16 g_Ml[A8M];

// ============================ PTX helpers ====================================
__device__ __forceinline__ uint32_t smem_u32(const void* p) {
    uint32_t a;
    asm("{ .reg .u64 t; cvta.to.shared.u64 t, %1; cvt.u32.u64 %0, t; }"
        : "=r"(a) : "l"(p));
    return a;
}
__device__ __forceinline__ float ex2f(float x) {
    float y;
    asm("ex2.approx.ftz.f32 %0, %1;" : "=f"(y) : "f"(x));
    return y;
}

#define LDSM4(R0, R1, R2, R3, ADDR) \
    asm volatile("ldmatrix.sync.aligned.m8n8.x4.shared.b16 {%0,%1,%2,%3}, [%4];" \
                 : "=r"(R0), "=r"(R1), "=r"(R2), "=r"(R3) : "r"(ADDR))
#define LDSM4T(R0, R1, R2, R3, ADDR) \
    asm volatile("ldmatrix.sync.aligned.m8n8.x4.trans.shared.b16 {%0,%1,%2,%3}, [%4];" \
                 : "=r"(R0), "=r"(R1), "=r"(R2), "=r"(R3) : "r"(ADDR))

#define MMA_BF16(C, A, B0, B1) \
    asm volatile("mma.sync.aligned.m16n8k16.row.col.f32.bf16.bf16.f32 " \
                 "{%0,%1,%2,%3}, {%4,%5,%6,%7}, {%8,%9}, {%0,%1,%2,%3};" \
                 : "+f"((C)[0]), "+f"((C)[1]), "+f"((C)[2]), "+f"((C)[3]) \
                 : "r"((A)[0]), "r"((A)[1]), "r"((A)[2]), "r"((A)[3]), \
                   "r"(B0), "r"(B1))

#define CP_A16(DST, SRC) \
    asm volatile("cp.async.cg.shared.global [%0], [%1], 16;" \
                 :: "r"(DST), "l"(SRC) : "memory")
#define CP_COMMIT() asm volatile("cp.async.commit_group;" ::: "memory")
#define CP_WAIT0()  asm volatile("cp.async.wait_group 0;" ::: "memory")
#define CP_WAIT1()  asm volatile("cp.async.wait_group 1;" ::: "memory")

__device__ __forceinline__ void bsplit4(float4 v, uint2& hi, uint2& lo) {
    __nv_bfloat16 h0 = __float2bfloat16(v.x);
    __nv_bfloat16 h1 = __float2bfloat16(v.y);
    __nv_bfloat16 h2 = __float2bfloat16(v.z);
    __nv_bfloat16 h3 = __float2bfloat16(v.w);
    __nv_bfloat16 l0 = __float2bfloat16(v.x - __bfloat162float(h0));
    __nv_bfloat16 l1 = __float2bfloat16(v.y - __bfloat162float(h1));
    __nv_bfloat16 l2 = __float2bfloat16(v.z - __bfloat162float(h2));
    __nv_bfloat16 l3 = __float2bfloat16(v.w - __bfloat162float(h3));
    hi.x = ((uint32_t)__bfloat16_as_ushort(h1) << 16) | __bfloat16_as_ushort(h0);
    hi.y = ((uint32_t)__bfloat16_as_ushort(h3) << 16) | __bfloat16_as_ushort(h2);
    lo.x = ((uint32_t)__bfloat16_as_ushort(l1) << 16) | __bfloat16_as_ushort(l0);
    lo.y = ((uint32_t)__bfloat16_as_ushort(l3) << 16) | __bfloat16_as_ushort(l2);
}
__device__ __forceinline__ void psplit2(float a, float b, uint32_t& hi, uint32_t& lo) {
    __nv_bfloat16 ha = __float2bfloat16(a), hb = __float2bfloat16(b);
    __nv_bfloat16 la = __float2bfloat16(a - __bfloat162float(ha));
    __nv_bfloat16 lb = __float2bfloat16(b - __bfloat162float(hb));
    hi = ((uint32_t)__bfloat16_as_ushort(hb) << 16) | __bfloat16_as_ushort(ha);
    lo = ((uint32_t)__bfloat16_as_ushort(lb) << 16) | __bfloat16_as_ushort(la);
}

#define QSCALE 0.18033688011112042f

// ============================================================================
// Fused splitters
// ============================================================================
__global__ void split_inputs(const float* __restrict__ q,
                             const float* __restrict__ k,
                             const float* __restrict__ v)
{
    const size_t n4 = A8M >> 2;
    size_t i = (size_t)blockIdx.x * blockDim.x + threadIdx.x;
    int plane = (int)(i / n4);
    size_t j = i - (size_t)plane * n4;
    const float* src = (plane == 0) ? q : (plane == 1) ? k : v;
    float4 vv = ((const float4*)src)[j];
    uint2 hi, lo;
    bsplit4(vv, hi, lo);
    ((uint2*)g_Ah)[i] = hi;
    ((uint2*)g_Al)[i] = lo;
}
__global__ void split_weights(const float* __restrict__ w0,
                              const float* __restrict__ w1,
                              const float* __restrict__ w2,
                              const float* __restrict__ w3)
{
    const size_t n4 = W1M >> 2;
    size_t i = (size_t)blockIdx.x * blockDim.x + threadIdx.x;
    int plane = (int)(i / n4);
    size_t j = i - (size_t)plane * n4;
    const float* src = (plane == 0) ? w0 : (plane == 1) ? w1 : (plane == 2) ? w2 : w3;
    float4 vv = ((const float4*)src)[j];
    uint2 hi, lo;
    bsplit4(vv, hi, lo);
    ((uint2*)g_Wph)[i] = hi;
    ((uint2*)g_Wpl)[i] = lo;
}

// Stage layout (GEMM): rows of 32 bf16 (64B) + 16B pad.
#define ROWB   80
#define TILEB  (128 * ROWB)
#define OFF_AHI 0
#define OFF_ALO (TILEB)
#define OFF_WHI (2 * TILEB)
#define OFF_WLO (3 * TILEB)
#define STAGEB  (4 * TILEB)
#define GSMEM_TOTAL (2 * STAGEB)  // 81920

// ============================================================================
// Shared GEMM body. Per k-step: ALL frags loaded upfront (12 LDSM, no
// duplicate W-hi load), then 48 MMAs in 3 product blocks (acc distance 16).
// ============================================================================
__device__ __forceinline__ void gemm_body(
    const __nv_bfloat16* __restrict__ Ah, const __nv_bfloat16* __restrict__ Al,
    const __nv_bfloat16* __restrict__ Wh, const __nv_bfloat16* __restrict__ Wl,
    const float* __restrict__ bias, float* __restrict__ Cext,
    int dstsel, char* dsm)
{
    const uint32_t sbase = smem_u32(dsm);
    __shared__ float s_bias[128];

    const int t    = threadIdx.x;
    const int wid  = t >> 5;
    const int lane = t & 31;
    const int m0 = blockIdx.y * 128;
    const int n0 = blockIdx.x * 128;
    const int wm0 = (wid >> 2) * 64;
    const int wn0 = (wid & 3) * 32;

    if (t < 32) ((float4*)s_bias)[t] = *(const float4*)&bias[n0 + t * 4];

    const uint32_t offA = (uint32_t)(wm0 + (lane & 15)) * ROWB
                        + (uint32_t)((lane >> 4) * 8) * 2;
    const uint32_t offB = (uint32_t)(wn0 + ((lane >> 4) & 1) * 8 + (lane & 7)) * ROWB
                        + (uint32_t)(((lane >> 3) & 1) * 8) * 2;

    float acc[4][4][4];
    #pragma unroll
    for (int i = 0; i < 4; i++)
        #pragma unroll
        for (int j = 0; j < 4; j++)
            #pragma unroll
            for (int r = 0; r < 4; r++) acc[i][j][r] = 0.0f;

    auto stage = [&](int c, int bufsel) {
        const int k0 = c * 32;
        const uint32_t dstb = sbase + (uint32_t)bufsel * STAGEB;
        #pragma unroll
        for (int i = 0; i < 8; i++) {
            int f   = i * 256 + t;
            int p   = f >> 9;
            int cc  = f & 511;
            int row = cc >> 2;
            int qq  = cc & 3;
            uint32_t dst = dstb + (uint32_t)p * TILEB + (uint32_t)row * ROWB + (uint32_t)qq * 16;
            const __nv_bfloat16* src;
            if (p == 0)      src = Ah + (size_t)(m0 + row) * ND + k0 + qq * 8;
            else if (p == 1) src = Al + (size_t)(m0 + row) * ND + k0 + qq * 8;
            else if (p == 2) src = Wh + (size_t)(n0 + row) * ND + k0 + qq * 8;
            else             src = Wl + (size_t)(n0 + row) * ND + k0 + qq * 8;
            CP_A16(dst, src);
        }
        CP_COMMIT();
    };

    stage(0, 0);
    stage(1, 1);

    for (int c = 0; c < 32; c++) {
        if (c < 31) { CP_WAIT1(); } else { CP_WAIT0(); }
        __syncthreads();
        const uint32_t sb = sbase + (uint32_t)(c & 1) * STAGEB;

        #pragma unroll
        for (int ks = 0; ks < 2; ks++) {
            const uint32_t ka = (uint32_t)ks * 32;
            uint32_t ah[16], al[16];
            uint32_t bh[8], bl[8];

            // ---- all frag loads upfront ----
            #pragma unroll
            for (int mi = 0; mi < 4; mi++)
                LDSM4(ah[mi*4+0], ah[mi*4+1], ah[mi*4+2], ah[mi*4+3],
                      sb + OFF_AHI + offA + ka + (uint32_t)mi * (16 * ROWB));
            #pragma unroll
            for (int nj = 0; nj < 2; nj++)
                LDSM4(bh[nj*4+0], bh[nj*4+1], bh[nj*4+2], bh[nj*4+3],
                      sb + OFF_WHI + offB + ka + (uint32_t)nj * (16 * ROWB));
            #pragma unroll
            for (int mi = 0; mi < 4; mi++)
                LDSM4(al[mi*4+0], al[mi*4+1], al[mi*4+2], al[mi*4+3],
                      sb + OFF_ALO + offA + ka + (uint32_t)mi * (16 * ROWB));
            #pragma unroll
            for (int nj = 0; nj < 2; nj++)
                LDSM4(bl[nj*4+0], bl[nj*4+1], bl[nj*4+2], bl[nj*4+3],
                      sb + OFF_WLO + offB + ka + (uint32_t)nj * (16 * ROWB));

            // ---- hh ----
            #pragma unroll
            for (int mi = 0; mi < 4; mi++)
                #pragma unroll
                for (int ni = 0; ni < 4; ni++)
                    MMA_BF16(acc[mi][ni], &ah[mi*4],
                             bh[(ni >> 1) * 4 + (ni & 1) * 2],
                             bh[(ni >> 1) * 4 + (ni & 1) * 2 + 1]);
            // ---- lh ----
            #pragma unroll
            for (int mi = 0; mi < 4; mi++)
                #pragma unroll
                for (int ni = 0; ni < 4; ni++)
                    MMA_BF16(acc[mi][ni], &al[mi*4],
                             bh[(ni >> 1) * 4 + (ni & 1) * 2],
                             bh[(ni >> 1) * 4 + (ni & 1) * 2 + 1]);
            // ---- hl ----
            #pragma unroll
            for (int mi = 0; mi < 4; mi++)
                #pragma unroll
                for (int ni = 0; ni < 4; ni++)
                    MMA_BF16(acc[mi][ni], &ah[mi*4],
                             bl[(ni >> 1) * 4 + (ni & 1) * 2],
                             bl[(ni >> 1) * 4 + (ni & 1) * 2 + 1]);
        }
        __syncthreads();
        if (c + 2 < 32) stage(c + 2, c & 1);
    }

    // ---- epilogue ----
    const int cr = lane >> 2;
    const int cc2 = (lane & 3) * 2;
    if (dstsel < 3) {
        const float qs = (dstsel == 0) ? QSCALE : 1.0f;
        __nv_bfloat16* Ph = (dstsel == 0) ? g_Qh : (dstsel == 1) ? g_Kh : g_Vh;
        __nv_bfloat16* Pl = (dstsel == 0) ? g_Ql : (dstsel == 1) ? g_Kl : g_Vl;
        #pragma unroll
        for (int mi = 0; mi < 4; mi++) {
            const int r0 = m0 + wm0 + mi * 16 + cr;
            #pragma unroll
            for (int ni = 0; ni < 4; ni++) {
                const int col = wn0 + ni * 8 + cc2;
                const float b0 = s_bias[col];
                const float b1 = s_bias[col + 1];
                float v0 = (acc[mi][ni][0] + b0) * qs;
                float v1 = (acc[mi][ni][1] + b1) * qs;
                float v2 = (acc[mi][ni][2] + b0) * qs;
                float v3 = (acc[mi][ni][3] + b1) * qs;
                uint32_t hi, lo;
                psplit2(v0, v1, hi, lo);
                *(uint32_t*)&Ph[(size_t)r0 * ND + n0 + col] = hi;
                *(uint32_t*)&Pl[(size_t)r0 * ND + n0 + col] = lo;
                psplit2(v2, v3, hi, lo);
                *(uint32_t*)&Ph[(size_t)(r0 + 8) * ND + n0 + col] = hi;
                *(uint32_t*)&Pl[(size_t)(r0 + 8) * ND + n0 + col] = lo;
            }
        }
    } else {
        #pragma unroll
        for (int mi = 0; mi < 4; mi++) {
            const int r0 = m0 + wm0 + mi * 16 + cr;
            #pragma unroll
            for (int ni = 0; ni < 4; ni++) {
                const int col = wn0 + ni * 8 + cc2;
                const float b0 = s_bias[col];
                const float b1 = s_bias[col + 1];
                float2 o0, o1;
                o0.x = acc[mi][ni][0] + b0;
                o0.y = acc[mi][ni][1] + b1;
                o1.x = acc[mi][ni][2] + b0;
                o1.y = acc[mi][ni][3] + b1;
                *(float2*)&Cext[(size_t)r0 * ND + n0 + col] = o0;
                *(float2*)&Cext[(size_t)(r0 + 8) * ND + n0 + col] = o1;
            }
        }
    }
}

__global__ __launch_bounds__(256, 2) void gemm_qkv(
    const float* __restrict__ bq, const float* __restrict__ bk,
    const float* __restrict__ bv)
{
    extern __shared__ char dsm[];
    const int z = blockIdx.z;
    const __nv_bfloat16* Ah = g_Ah + (size_t)z * A8M;
    const __nv_bfloat16* Al = g_Al + (size_t)z * A8M;
    const __nv_bfloat16* Wh = g_Wph + (size_t)z * W1M;
    const __nv_bfloat16* Wl = g_Wpl + (size_t)z * W1M;
    const float* bias = (z == 0) ? bq : (z == 1) ? bk : bv;
    gemm_body(Ah, Al, Wh, Wl, bias, nullptr, z, dsm);
}

__global__ __launch_bounds__(256, 2) void gemm_o(
    const float* __restrict__ bias, float* __restrict__ out)
{
    extern __shared__ char dsm[];
    gemm_body(g_Mh, g_Ml, g_Wph + 3 * W1M, g_Wpl + 3 * W1M, bias, out, 3, dsm);
}

// ============================================================================
// Tensor-core flash attention (R13 macro-structure: 2-buffer cp.async,
// 2 CTAs/SM) with product-outer MMA ordering (acc dep distance 2 -> 8).
// Grid (B*NH, NS/128), 256 threads (8 warps x 16 Q rows).
// ============================================================================
#define AROWB 144           // 64 bf16 (128B) + 16B pad
#define KVB   36864         // one K/V buffer: 4 planes x 64 x 144
#define OKH 0
#define OKL 9216
#define OVH 18432
#define OVL 27648
#define ASMEM_TOTAL (2 * KVB)   // 73728 -> 2 CTAs/SM

__global__ __launch_bounds__(256, 2) void attn_tc(float* __restrict__ ctx_out)
{
    extern __shared__ char sm[];
    const uint32_t sb = smem_u32(sm);
    const int t = threadIdx.x, wid = t >> 5, lane = t & 31;
    const int b = blockIdx.x >> 4, h = blockIdx.x & 15;
    const int q0 = blockIdx.y * 128;

    // ---- stage Q tile (128 x 64, hi/lo) via cp.async, then load frags ----
    #pragma unroll
    for (int i = 0; i < 8; i++) {
        int f   = i * 256 + t;
        int p   = f >> 10;
        int cc  = f & 1023;
        int row = cc >> 3;
        int qq  = cc & 7;
        uint32_t dst = sb + (uint32_t)p * 18432 + (uint32_t)row * AROWB + (uint32_t)qq * 16;
        const __nv_bfloat16* src = ((p == 0) ? g_Qh : g_Ql)
                                 + ((size_t)b * NS + q0 + row) * ND + h * 64 + qq * 8;
        CP_A16(dst, src);
    }
    CP_COMMIT();
    CP_WAIT0();
    __syncthreads();

    uint32_t qh[4][4], ql[4][4];
    const uint32_t offA = (uint32_t)(wid * 16 + (lane & 15)) * AROWB
                        + (uint32_t)((lane >> 4) * 8) * 2;
    #pragma unroll
    for (int ks = 0; ks < 4; ks++) {
        LDSM4(qh[ks][0], qh[ks][1], qh[ks][2], qh[ks][3], sb + offA + ks * 32);
        LDSM4(ql[ks][0], ql[ks][1], ql[ks][2], ql[ks][3], sb + 18432 + offA + ks * 32);
    }
    __syncthreads();   // Q frags in regs; buffers may be reused now

    float ctx[8][4];
    #pragma unroll
    for (int i = 0; i < 8; i++)
        #pragma unroll
        for (int j = 0; j < 4; j++) ctx[i][j] = 0.0f;
    float m0 = -1e30f, m1 = -1e30f, l0 = 0.0f, l1 = 0.0f;

    const uint32_t offBs = (uint32_t)(((lane >> 4) & 1) * 8 + (lane & 7)) * AROWB
                         + (uint32_t)(((lane >> 3) & 1) * 8) * 2;
    const uint32_t offBt = (uint32_t)(lane & 15) * AROWB + (uint32_t)((lane >> 4) * 8) * 2;

    auto stage_kv = [&](int kt, int bufsel) {
        const uint32_t dstb = sb + (uint32_t)bufsel * KVB;
        #pragma unroll
        for (int i = 0; i < 8; i++) {
            int f   = i * 256 + t;
            int p   = f >> 9;
            int cc  = f & 511;
            int row = cc >> 3;
            int qq  = cc & 7;
            uint32_t dst = dstb + (uint32_t)p * 9216 + (uint32_t)row * AROWB + (uint32_t)qq * 16;
            const __nv_bfloat16* base =
                (p == 0) ? g_Kh : (p == 1) ? g_Kl : (p == 2) ? g_Vh : g_Vl;
            const __nv_bfloat16* src = base
                + ((size_t)b * NS + kt * 64 + row) * ND + h * 64 + qq * 8;
            CP_A16(dst, src);
        }
        CP_COMMIT();
    };

    stage_kv(0, 0);
    stage_kv(1, 1);

    for (int kt = 0; kt < NS / 64; kt++) {
        if (kt < 31) { CP_WAIT1(); } else { CP_WAIT0(); }
        __syncthreads();
        const uint32_t kb = sb + (uint32_t)(kt & 1) * KVB;

        // ---- scores: S = Q . K^T  (product-outer ordering) ----
        float s[8][4];
        #pragma unroll
        for (int i = 0; i < 8; i++)
            #pragma unroll
            for (int j = 0; j < 4; j++) s[i][j] = 0.0f;

        #pragma unroll
        for (int ks = 0; ks < 4; ks++) {
            uint32_t kf[16], lf[16];
            #pragma unroll
            for (int nbp = 0; nbp < 4; nbp++) {
                uint32_t a = kb + (uint32_t)nbp * (16 * AROWB) + (uint32_t)ks * 32 + offBs;
                LDSM4(kf[nbp*4+0], kf[nbp*4+1], kf[nbp*4+2], kf[nbp*4+3], a + OKH);
                LDSM4(lf[nbp*4+0], lf[nbp*4+1], lf[nbp*4+2], lf[nbp*4+3], a + OKL);
            }
            // hh over all nbp
            #pragma unroll
            for (int nbp = 0; nbp < 4; nbp++) {
                MMA_BF16(s[2*nbp],   qh[ks], kf[nbp*4+0], kf[nbp*4+1]);
                MMA_BF16(s[2*nbp+1], qh[ks], kf[nbp*4+2], kf[nbp*4+3]);
            }
            // hl over all nbp
            #pragma unroll
            for (int nbp = 0; nbp < 4; nbp++) {
                MMA_BF16(s[2*nbp],   qh[ks], lf[nbp*4+0], lf[nbp*4+1]);
                MMA_BF16(s[2*nbp+1], qh[ks], lf[nbp*4+2], lf[nbp*4+3]);
            }
            // lh over all nbp
            #pragma unroll
            for (int nbp = 0; nbp < 4; nbp++) {
                MMA_BF16(s[2*nbp],   ql[ks], kf[nbp*4+0], kf[nbp*4+1]);
                MMA_BF16(s[2*nbp+1], ql[ks], kf[nbp*4+2], kf[nbp*4+3]);
            }
        }

        // ---- online softmax (log2 domain) ----
        float mn0 = s[0][0], mn1 = s[0][2];
        #pragma unroll
        for (int nb = 0; nb < 8; nb++) {
            mn0 = fmaxf(mn0, fmaxf(s[nb][0], s[nb][1]));
            mn1 = fmaxf(mn1, fmaxf(s[nb][2], s[nb][3]));
        }
        mn0 = fmaxf(mn0, __shfl_xor_sync(0xffffffffu, mn0, 1));
        mn0 = fmaxf(mn0, __shfl_xor_sync(0xffffffffu, mn0, 2));
        mn1 = fmaxf(mn1, __shfl_xor_sync(0xffffffffu, mn1, 1));
        mn1 = fmaxf(mn1, __shfl_xor_sync(0xffffffffu, mn1, 2));
        float nm0 = fmaxf(m0, mn0), nm1 = fmaxf(m1, mn1);
        float c0 = ex2f(m0 - nm0), c1 = ex2f(m1 - nm1);
        m0 = nm0; m1 = nm1;

        float sum0 = 0.0f, sum1 = 0.0f;
        #pragma unroll
        for (int nb = 0; nb < 8; nb++) {
            s[nb][0] = ex2f(s[nb][0] - m0);
            s[nb][1] = ex2f(s[nb][1] - m0);
            s[nb][2] = ex2f(s[nb][2] - m1);
            s[nb][3] = ex2f(s[nb][3] - m1);
            sum0 += s[nb][0] + s[nb][1];
            sum1 += s[nb][2] + s[nb][3];
        }
        sum0 += __shfl_xor_sync(0xffffffffu, sum0, 1);
        sum0 += __shfl_xor_sync(0xffffffffu, sum0, 2);
        sum1 += __shfl_xor_sync(0xffffffffu, sum1, 1);
        sum1 += __shfl_xor_sync(0xffffffffu, sum1, 2);
        l0 = l0 * c0 + sum0;
        l1 = l1 * c1 + sum1;
        #pragma unroll
        for (int db = 0; db < 8; db++) {
            ctx[db][0] *= c0; ctx[db][1] *= c0;
            ctx[db][2] *= c1; ctx[db][3] *= c1;
        }

        // ---- ctx += P . V  (per-ks P split + product-outer ordering) ----
        #pragma unroll
        for (int ks = 0; ks < 4; ks++) {
            uint32_t ph[4], pl[4];
            const int e = 2 * ks, o = 2 * ks + 1;
            psplit2(s[e][0], s[e][1], ph[0], pl[0]);
            psplit2(s[e][2], s[e][3], ph[1], pl[1]);
            psplit2(s[o][0], s[o][1], ph[2], pl[2]);
            psplit2(s[o][2], s[o][3], ph[3], pl[3]);

            uint32_t vf[16], wf[16];
            #pragma unroll
            for (int dbp = 0; dbp < 4; dbp++) {
                uint32_t a = kb + (uint32_t)ks * (16 * AROWB) + (uint32_t)dbp * 32 + offBt;
                LDSM4T(vf[dbp*4+0], vf[dbp*4+1], vf[dbp*4+2], vf[dbp*4+3], a + OVH);
                LDSM4T(wf[dbp*4+0], wf[dbp*4+1], wf[dbp*4+2], wf[dbp*4+3], a + OVL);
            }
            // ph * vh
            #pragma unroll
            for (int dbp = 0; dbp < 4; dbp++) {
                MMA_BF16(ctx[2*dbp],   ph, vf[dbp*4+0], vf[dbp*4+1]);
                MMA_BF16(ctx[2*dbp+1], ph, vf[dbp*4+2], vf[dbp*4+3]);
            }
            // ph * vl
            #pragma unroll
            for (int dbp = 0; dbp < 4; dbp++) {
                MMA_BF16(ctx[2*dbp],   ph, wf[dbp*4+0], wf[dbp*4+1]);
                MMA_BF16(ctx[2*dbp+1], ph, wf[dbp*4+2], wf[dbp*4+3]);
            }
            // pl * vh
            #pragma unroll
            for (int dbp = 0; dbp < 4; dbp++) {
                MMA_BF16(ctx[2*dbp],   pl, vf[dbp*4+0], vf[dbp*4+1]);
                MMA_BF16(ctx[2*dbp+1], pl, vf[dbp*4+2], vf[dbp*4+3]);
            }
        }
        __syncthreads();
        if (kt + 2 < NS / 64) stage_kv(kt + 2, kt & 1);
    }

    // ---- epilogue: ctx (fp32) + merged split planes ----
    const float i0 = 1.0f / l0, i1 = 1.0f / l1;
    const int r0 = q0 + wid * 16 + (lane >> 2);
    #pragma unroll
    for (int db = 0; db < 8; db++) {
        const int col = db * 8 + (lane & 3) * 2;
        float2 o0, o1;
        o0.x = ctx[db][0] * i0; o0.y = ctx[db][1] * i0;
        o1.x = ctx[db][2] * i1; o1.y = ctx[db][3] * i1;
        *(float2*)&ctx_out[(((size_t)b * NH + h) * NS + r0) * NHD + col]     = o0;
        *(float2*)&ctx_out[(((size_t)b * NH + h) * NS + r0 + 8) * NHD + col] = o1;
        uint32_t hi, lo;
        psplit2(o0.x, o0.y, hi, lo);
        *(uint32_t*)&g_Mh[((size_t)b * NS + r0) * ND + h * NHD + col] = hi;
        *(uint32_t*)&g_Ml[((size_t)b * NS + r0) * ND + h * NHD + col] = lo;
        psplit2(o1.x, o1.y, hi, lo);
        *(uint32_t*)&g_Mh[((size_t)b * NS + r0 + 8) * ND + h * NHD + col] = hi;
        *(uint32_t*)&g_Ml[((size_t)b * NS + r0 + 8) * ND + h * NHD + col] = lo;
    }
}

// ----------------------------------------------------------------------------
extern "C" void kernel_launch(void* const* d_in, const int* in_sizes, int n_in,
                              void* d_out, int out_size)
{
    (void)in_sizes; (void)n_in; (void)out_size;
    const float* q    = (const float*)d_in[0];
    const float* k    = (const float*)d_in[1];
    const float* v    = (const float*)d_in[2];
    const float* wq_w = (const float*)d_in[3];
    const float* wq_b = (const float*)d_in[4];
    const float* wk_w = (const float*)d_in[5];
    const float* wk_b = (const float*)d_in[6];
    const float* wv_w = (const float*)d_in[7];
    const float* wv_b = (const float*)d_in[8];
    const float* wo_w = (const float*)d_in[9];
    const float* wo_b = (const float*)d_in[10];

    float* out = (float*)d_out;                    // [B,S,D]
    float* ctx = out + (size_t)NM * ND;            // [B,H,S,HD]

    cudaFuncSetAttribute(gemm_qkv, cudaFuncAttributeMaxDynamicSharedMemorySize,
                         GSMEM_TOTAL);
    cudaFuncSetAttribute(gemm_o, cudaFuncAttributeMaxDynamicSharedMemorySize,
                         GSMEM_TOTAL);
    cudaFuncSetAttribute(attn_tc, cudaFuncAttributeMaxDynamicSharedMemorySize,
                         ASMEM_TOTAL);

    split_inputs<<<(unsigned)(3 * (A8M >> 2) / 256), 256>>>(q, k, v);
    split_weights<<<(unsigned)(4 * (W1M >> 2) / 256), 256>>>(wq_w, wk_w, wv_w, wo_w);

    dim3 gqkv(ND / 128, NM / 128, 3);              // (8, 64, 3)
    gemm_qkv<<<gqkv, 256, GSMEM_TOTAL>>>(wq_b, wk_b, wv_b);   // -> Q/K/V planes

    attn_tc<<<dim3(NB * NH, NS / 128), 256, ASMEM_TOTAL>>>(ctx); // -> ctx + merged

    dim3 go(ND / 128, NM / 128);                   // (8, 64)
    gemm_o<<<go, 256, GSMEM_TOTAL>>>(wo_b, out);   // -> out
}

// round 16
// speedup vs baseline: 1.0461x; 1.0083x over previous
#include <cuda_runtime.h>
#include <cuda_bf16.h>
#include <cstdint>
#include <math.h>

// Problem shape (fixed)
#define NB  4
#define NS  2048
#define ND  1024
#define NH  16
#define NHD 64
#define NM  (NB * NS)   // 8192 rows
#define A8M ((size_t)NM * ND)    // 8388608
#define W1M ((size_t)ND * ND)    // 1048576

// ---- Scratch (device globals: allocation-free) ----
__device__ __nv_bfloat16 g_Ah[3 * A8M];
__device__ __nv_bfloat16 g_Al[3 * A8M];
__device__ __nv_bfloat16 g_Wph[4 * W1M];
__device__ __nv_bfloat16 g_Wpl[4 * W1M];
__device__ __nv_bfloat16 g_Qh[A8M];
__device__ __nv_bfloat16 g_Ql[A8M];
__device__ __nv_bfloat16 g_Kh[A8M];
__device__ __nv_bfloat16 g_Kl[A8M];
__device__ __nv_bfloat16 g_Vh[A8M];
__device__ __nv_bfloat16 g_Vl[A8M];
__device__ __nv_bfloat16 g_Mh[A8M];
__device__ __nv_bfloat16 g_Ml[A8M];

// ============================ PTX helpers ====================================
__device__ __forceinline__ uint32_t smem_u32(const void* p) {
    uint32_t a;
    asm("{ .reg .u64 t; cvta.to.shared.u64 t, %1; cvt.u32.u64 %0, t; }"
        : "=r"(a) : "l"(p));
    return a;
}
__device__ __forceinline__ float ex2f(float x) {
    float y;
    asm("ex2.approx.ftz.f32 %0, %1;" : "=f"(y) : "f"(x));
    return y;
}

#define LDSM4(R0, R1, R2, R3, ADDR) \
    asm volatile("ldmatrix.sync.aligned.m8n8.x4.shared.b16 {%0,%1,%2,%3}, [%4];" \
                 : "=r"(R0), "=r"(R1), "=r"(R2), "=r"(R3) : "r"(ADDR))
#define LDSM4T(R0, R1, R2, R3, ADDR) \
    asm volatile("ldmatrix.sync.aligned.m8n8.x4.trans.shared.b16 {%0,%1,%2,%3}, [%4];" \
                 : "=r"(R0), "=r"(R1), "=r"(R2), "=r"(R3) : "r"(ADDR))

#define MMA_BF16(C, A, B0, B1) \
    asm volatile("mma.sync.aligned.m16n8k16.row.col.f32.bf16.bf16.f32 " \
                 "{%0,%1,%2,%3}, {%4,%5,%6,%7}, {%8,%9}, {%0,%1,%2,%3};" \
                 : "+f"((C)[0]), "+f"((C)[1]), "+f"((C)[2]), "+f"((C)[3]) \
                 : "r"((A)[0]), "r"((A)[1]), "r"((A)[2]), "r"((A)[3]), \
                   "r"(B0), "r"(B1))

#define CP_A16(DST, SRC) \
    asm volatile("cp.async.cg.shared.global [%0], [%1], 16;" \
                 :: "r"(DST), "l"(SRC) : "memory")
#define CP_COMMIT() asm volatile("cp.async.commit_group;" ::: "memory")
#define CP_WAIT0()  asm volatile("cp.async.wait_group 0;" ::: "memory")
#define CP_WAIT1()  asm volatile("cp.async.wait_group 1;" ::: "memory")

__device__ __forceinline__ void bsplit4(float4 v, uint2& hi, uint2& lo) {
    __nv_bfloat16 h0 = __float2bfloat16(v.x);
    __nv_bfloat16 h1 = __float2bfloat16(v.y);
    __nv_bfloat16 h2 = __float2bfloat16(v.z);
    __nv_bfloat16 h3 = __float2bfloat16(v.w);
    __nv_bfloat16 l0 = __float2bfloat16(v.x - __bfloat162float(h0));
    __nv_bfloat16 l1 = __float2bfloat16(v.y - __bfloat162float(h1));
    __nv_bfloat16 l2 = __float2bfloat16(v.z - __bfloat162float(h2));
    __nv_bfloat16 l3 = __float2bfloat16(v.w - __bfloat162float(h3));
    hi.x = ((uint32_t)__bfloat16_as_ushort(h1) << 16) | __bfloat16_as_ushort(h0);
    hi.y = ((uint32_t)__bfloat16_as_ushort(h3) << 16) | __bfloat16_as_ushort(h2);
    lo.x = ((uint32_t)__bfloat16_as_ushort(l1) << 16) | __bfloat16_as_ushort(l0);
    lo.y = ((uint32_t)__bfloat16_as_ushort(l3) << 16) | __bfloat16_as_ushort(l2);
}
__device__ __forceinline__ void psplit2(float a, float b, uint32_t& hi, uint32_t& lo) {
    __nv_bfloat16 ha = __float2bfloat16(a), hb = __float2bfloat16(b);
    __nv_bfloat16 la = __float2bfloat16(a - __bfloat162float(ha));
    __nv_bfloat16 lb = __float2bfloat16(b - __bfloat162float(hb));
    hi = ((uint32_t)__bfloat16_as_ushort(hb) << 16) | __bfloat16_as_ushort(ha);
    lo = ((uint32_t)__bfloat16_as_ushort(lb) << 16) | __bfloat16_as_ushort(la);
}

#define QSCALE 0.18033688011112042f

// ============================================================================
// Fused splitters
// ============================================================================
__global__ void split_inputs(const float* __restrict__ q,
                             const float* __restrict__ k,
                             const float* __restrict__ v)
{
    const size_t n4 = A8M >> 2;
    size_t i = (size_t)blockIdx.x * blockDim.x + threadIdx.x;
    int plane = (int)(i / n4);
    size_t j = i - (size_t)plane * n4;
    const float* src = (plane == 0) ? q : (plane == 1) ? k : v;
    float4 vv = ((const float4*)src)[j];
    uint2 hi, lo;
    bsplit4(vv, hi, lo);
    ((uint2*)g_Ah)[i] = hi;
    ((uint2*)g_Al)[i] = lo;
}
__global__ void split_weights(const float* __restrict__ w0,
                              const float* __restrict__ w1,
                              const float* __restrict__ w2,
                              const float* __restrict__ w3)
{
    const size_t n4 = W1M >> 2;
    size_t i = (size_t)blockIdx.x * blockDim.x + threadIdx.x;
    int plane = (int)(i / n4);
    size_t j = i - (size_t)plane * n4;
    const float* src = (plane == 0) ? w0 : (plane == 1) ? w1 : (plane == 2) ? w2 : w3;
    float4 vv = ((const float4*)src)[j];
    uint2 hi, lo;
    bsplit4(vv, hi, lo);
    ((uint2*)g_Wph)[i] = hi;
    ((uint2*)g_Wpl)[i] = lo;
}

// Stage layout (GEMM): rows of 32 bf16 (64B) + 16B pad.
#define ROWB   80
#define TILEB  (128 * ROWB)
#define OFF_AHI 0
#define OFF_ALO (TILEB)
#define OFF_WHI (2 * TILEB)
#define OFF_WLO (3 * TILEB)
#define STAGEB  (4 * TILEB)
#define GSMEM_TOTAL (2 * STAGEB)  // 81920

// ============================================================================
// Shared GEMM body (unchanged from R15: frag loads upfront, 3 product blocks).
// ============================================================================
__device__ __forceinline__ void gemm_body(
    const __nv_bfloat16* __restrict__ Ah, const __nv_bfloat16* __restrict__ Al,
    const __nv_bfloat16* __restrict__ Wh, const __nv_bfloat16* __restrict__ Wl,
    const float* __restrict__ bias, float* __restrict__ Cext,
    int dstsel, char* dsm)
{
    const uint32_t sbase = smem_u32(dsm);
    __shared__ float s_bias[128];

    const int t    = threadIdx.x;
    const int wid  = t >> 5;
    const int lane = t & 31;
    const int m0 = blockIdx.y * 128;
    const int n0 = blockIdx.x * 128;
    const int wm0 = (wid >> 2) * 64;
    const int wn0 = (wid & 3) * 32;

    if (t < 32) ((float4*)s_bias)[t] = *(const float4*)&bias[n0 + t * 4];

    const uint32_t offA = (uint32_t)(wm0 + (lane & 15)) * ROWB
                        + (uint32_t)((lane >> 4) * 8) * 2;
    const uint32_t offB = (uint32_t)(wn0 + ((lane >> 4) & 1) * 8 + (lane & 7)) * ROWB
                        + (uint32_t)(((lane >> 3) & 1) * 8) * 2;

    float acc[4][4][4];
    #pragma unroll
    for (int i = 0; i < 4; i++)
        #pragma unroll
        for (int j = 0; j < 4; j++)
            #pragma unroll
            for (int r = 0; r < 4; r++) acc[i][j][r] = 0.0f;

    auto stage = [&](int c, int bufsel) {
        const int k0 = c * 32;
        const uint32_t dstb = sbase + (uint32_t)bufsel * STAGEB;
        #pragma unroll
        for (int i = 0; i < 8; i++) {
            int f   = i * 256 + t;
            int p   = f >> 9;
            int cc  = f & 511;
            int row = cc >> 2;
            int qq  = cc & 3;
            uint32_t dst = dstb + (uint32_t)p * TILEB + (uint32_t)row * ROWB + (uint32_t)qq * 16;
            const __nv_bfloat16* src;
            if (p == 0)      src = Ah + (size_t)(m0 + row) * ND + k0 + qq * 8;
            else if (p == 1) src = Al + (size_t)(m0 + row) * ND + k0 + qq * 8;
            else if (p == 2) src = Wh + (size_t)(n0 + row) * ND + k0 + qq * 8;
            else             src = Wl + (size_t)(n0 + row) * ND + k0 + qq * 8;
            CP_A16(dst, src);
        }
        CP_COMMIT();
    };

    stage(0, 0);
    stage(1, 1);

    for (int c = 0; c < 32; c++) {
        if (c < 31) { CP_WAIT1(); } else { CP_WAIT0(); }
        __syncthreads();
        const uint32_t sb = sbase + (uint32_t)(c & 1) * STAGEB;

        #pragma unroll
        for (int ks = 0; ks < 2; ks++) {
            const uint32_t ka = (uint32_t)ks * 32;
            uint32_t ah[16], al[16];
            uint32_t bh[8], bl[8];

            #pragma unroll
            for (int mi = 0; mi < 4; mi++)
                LDSM4(ah[mi*4+0], ah[mi*4+1], ah[mi*4+2], ah[mi*4+3],
                      sb + OFF_AHI + offA + ka + (uint32_t)mi * (16 * ROWB));
            #pragma unroll
            for (int nj = 0; nj < 2; nj++)
                LDSM4(bh[nj*4+0], bh[nj*4+1], bh[nj*4+2], bh[nj*4+3],
                      sb + OFF_WHI + offB + ka + (uint32_t)nj * (16 * ROWB));
            #pragma unroll
            for (int mi = 0; mi < 4; mi++)
                LDSM4(al[mi*4+0], al[mi*4+1], al[mi*4+2], al[mi*4+3],
                      sb + OFF_ALO + offA + ka + (uint32_t)mi * (16 * ROWB));
            #pragma unroll
            for (int nj = 0; nj < 2; nj++)
                LDSM4(bl[nj*4+0], bl[nj*4+1], bl[nj*4+2], bl[nj*4+3],
                      sb + OFF_WLO + offB + ka + (uint32_t)nj * (16 * ROWB));

            #pragma unroll
            for (int mi = 0; mi < 4; mi++)
                #pragma unroll
                for (int ni = 0; ni < 4; ni++)
                    MMA_BF16(acc[mi][ni], &ah[mi*4],
                             bh[(ni >> 1) * 4 + (ni & 1) * 2],
                             bh[(ni >> 1) * 4 + (ni & 1) * 2 + 1]);
            #pragma unroll
            for (int mi = 0; mi < 4; mi++)
                #pragma unroll
                for (int ni = 0; ni < 4; ni++)
                    MMA_BF16(acc[mi][ni], &al[mi*4],
                             bh[(ni >> 1) * 4 + (ni & 1) * 2],
                             bh[(ni >> 1) * 4 + (ni & 1) * 2 + 1]);
            #pragma unroll
            for (int mi = 0; mi < 4; mi++)
                #pragma unroll
                for (int ni = 0; ni < 4; ni++)
                    MMA_BF16(acc[mi][ni], &ah[mi*4],
                             bl[(ni >> 1) * 4 + (ni & 1) * 2],
                             bl[(ni >> 1) * 4 + (ni & 1) * 2 + 1]);
        }
        __syncthreads();
        if (c + 2 < 32) stage(c + 2, c & 1);
    }

    // ---- epilogue ----
    const int cr = lane >> 2;
    const int cc2 = (lane & 3) * 2;
    if (dstsel < 3) {
        const float qs = (dstsel == 0) ? QSCALE : 1.0f;
        __nv_bfloat16* Ph = (dstsel == 0) ? g_Qh : (dstsel == 1) ? g_Kh : g_Vh;
        __nv_bfloat16* Pl = (dstsel == 0) ? g_Ql : (dstsel == 1) ? g_Kl : g_Vl;
        #pragma unroll
        for (int mi = 0; mi < 4; mi++) {
            const int r0 = m0 + wm0 + mi * 16 + cr;
            #pragma unroll
            for (int ni = 0; ni < 4; ni++) {
                const int col = wn0 + ni * 8 + cc2;
                const float b0 = s_bias[col];
                const float b1 = s_bias[col + 1];
                float v0 = (acc[mi][ni][0] + b0) * qs;
                float v1 = (acc[mi][ni][1] + b1) * qs;
                float v2 = (acc[mi][ni][2] + b0) * qs;
                float v3 = (acc[mi][ni][3] + b1) * qs;
                uint32_t hi, lo;
                psplit2(v0, v1, hi, lo);
                *(uint32_t*)&Ph[(size_t)r0 * ND + n0 + col] = hi;
                *(uint32_t*)&Pl[(size_t)r0 * ND + n0 + col] = lo;
                psplit2(v2, v3, hi, lo);
                *(uint32_t*)&Ph[(size_t)(r0 + 8) * ND + n0 + col] = hi;
                *(uint32_t*)&Pl[(size_t)(r0 + 8) * ND + n0 + col] = lo;
            }
        }
    } else {
        #pragma unroll
        for (int mi = 0; mi < 4; mi++) {
            const int r0 = m0 + wm0 + mi * 16 + cr;
            #pragma unroll
            for (int ni = 0; ni < 4; ni++) {
                const int col = wn0 + ni * 8 + cc2;
                const float b0 = s_bias[col];
                const float b1 = s_bias[col + 1];
                float2 o0, o1;
                o0.x = acc[mi][ni][0] + b0;
                o0.y = acc[mi][ni][1] + b1;
                o1.x = acc[mi][ni][2] + b0;
                o1.y = acc[mi][ni][3] + b1;
                *(float2*)&Cext[(size_t)r0 * ND + n0 + col] = o0;
                *(float2*)&Cext[(size_t)(r0 + 8) * ND + n0 + col] = o1;
            }
        }
    }
}

__global__ __launch_bounds__(256, 2) void gemm_qkv(
    const float* __restrict__ bq, const float* __restrict__ bk,
    const float* __restrict__ bv)
{
    extern __shared__ char dsm[];
    const int z = blockIdx.z;
    const __nv_bfloat16* Ah = g_Ah + (size_t)z * A8M;
    const __nv_bfloat16* Al = g_Al + (size_t)z * A8M;
    const __nv_bfloat16* Wh = g_Wph + (size_t)z * W1M;
    const __nv_bfloat16* Wl = g_Wpl + (size_t)z * W1M;
    const float* bias = (z == 0) ? bq : (z == 1) ? bk : bv;
    gemm_body(Ah, Al, Wh, Wl, bias, nullptr, z, dsm);
}

__global__ __launch_bounds__(256, 2) void gemm_o(
    const float* __restrict__ bias, float* __restrict__ out)
{
    extern __shared__ char dsm[];
    gemm_body(g_Mh, g_Ml, g_Wph + 3 * W1M, g_Wpl + 3 * W1M, bias, out, 3, dsm);
}

// ============================================================================
// Tensor-core flash attention: 3-buffer cp.async ring, ONE barrier per tile.
// stage(kt+2) targets buf (kt+2)%3 != buf kt%3 being computed, so the single
// barrier covers both WAR (stage vs last tile's reads) and RAW (tile kt data).
// smem/CTA = 3*36864 = 110592 -> 2 CTAs/SM (221 KB < 228 KB).
// Grid (B*NH, NS/128), 256 threads (8 warps x 16 Q rows).
// ============================================================================
#define AROWB 144           // 64 bf16 (128B) + 16B pad
#define KVB   36864         // one K/V buffer: 4 planes x 64 x 144
#define OKH 0
#define OKL 9216
#define OVH 18432
#define OVL 27648
#define ASMEM_TOTAL (3 * KVB)   // 110592

__global__ __launch_bounds__(256, 2) void attn_tc(float* __restrict__ ctx_out)
{
    extern __shared__ char sm[];
    const uint32_t sb = smem_u32(sm);
    const int t = threadIdx.x, wid = t >> 5, lane = t & 31;
    const int b = blockIdx.x >> 4, h = blockIdx.x & 15;
    const int q0 = blockIdx.y * 128;

    // ---- stage Q tile (128 x 64, hi/lo) via cp.async, then load frags ----
    #pragma unroll
    for (int i = 0; i < 8; i++) {
        int f   = i * 256 + t;
        int p   = f >> 10;
        int cc  = f & 1023;
        int row = cc >> 3;
        int qq  = cc & 7;
        uint32_t dst = sb + (uint32_t)p * 18432 + (uint32_t)row * AROWB + (uint32_t)qq * 16;
        const __nv_bfloat16* src = ((p == 0) ? g_Qh : g_Ql)
                                 + ((size_t)b * NS + q0 + row) * ND + h * 64 + qq * 8;
        CP_A16(dst, src);
    }
    CP_COMMIT();
    CP_WAIT0();
    __syncthreads();

    uint32_t qh[4][4], ql[4][4];
    const uint32_t offA = (uint32_t)(wid * 16 + (lane & 15)) * AROWB
                        + (uint32_t)((lane >> 4) * 8) * 2;
    #pragma unroll
    for (int ks = 0; ks < 4; ks++) {
        LDSM4(qh[ks][0], qh[ks][1], qh[ks][2], qh[ks][3], sb + offA + ks * 32);
        LDSM4(ql[ks][0], ql[ks][1], ql[ks][2], ql[ks][3], sb + 18432 + offA + ks * 32);
    }
    __syncthreads();   // Q frags in regs; buffer 0 region reusable

    float ctx[8][4];
    #pragma unroll
    for (int i = 0; i < 8; i++)
        #pragma unroll
        for (int j = 0; j < 4; j++) ctx[i][j] = 0.0f;
    float m0 = -1e30f, m1 = -1e30f, l0 = 0.0f, l1 = 0.0f;

    const uint32_t offBs = (uint32_t)(((lane >> 4) & 1) * 8 + (lane & 7)) * AROWB
                         + (uint32_t)(((lane >> 3) & 1) * 8) * 2;
    const uint32_t offBt = (uint32_t)(lane & 15) * AROWB + (uint32_t)((lane >> 4) * 8) * 2;

    auto stage_kv = [&](int kt, int bufsel) {
        const uint32_t dstb = sb + (uint32_t)bufsel * KVB;
        #pragma unroll
        for (int i = 0; i < 8; i++) {
            int f   = i * 256 + t;
            int p   = f >> 9;
            int cc  = f & 511;
            int row = cc >> 3;
            int qq  = cc & 7;
            uint32_t dst = dstb + (uint32_t)p * 9216 + (uint32_t)row * AROWB + (uint32_t)qq * 16;
            const __nv_bfloat16* base =
                (p == 0) ? g_Kh : (p == 1) ? g_Kl : (p == 2) ? g_Vh : g_Vl;
            const __nv_bfloat16* src = base
                + ((size_t)b * NS + kt * 64 + row) * ND + h * 64 + qq * 8;
            CP_A16(dst, src);
        }
        CP_COMMIT();
    };

    stage_kv(0, 0);
    stage_kv(1, 1);

    const int NT = NS / 64;   // 32
    for (int kt = 0; kt < NT; kt++) {
        // Own copies of tile kt done (1 newer group may stay in flight)...
        if (kt < NT - 1) { CP_WAIT1(); } else { CP_WAIT0(); }
        // ...barrier: ALL threads' tile-kt copies visible AND all reads of
        // buf (kt+2)%3 from iteration kt-1 are complete.
        __syncthreads();
        // Prefetch tile kt+2 into the ring slot not in use this iteration.
        if (kt + 2 < NT) stage_kv(kt + 2, (kt + 2) % 3);

        const uint32_t kb = sb + (uint32_t)(kt % 3) * KVB;

        // ---- scores: S = Q . K^T  (product-outer ordering) ----
        float s[8][4];
        #pragma unroll
        for (int i = 0; i < 8; i++)
            #pragma unroll
            for (int j = 0; j < 4; j++) s[i][j] = 0.0f;

        #pragma unroll
        for (int ks = 0; ks < 4; ks++) {
            uint32_t kf[16], lf[16];
            #pragma unroll
            for (int nbp = 0; nbp < 4; nbp++) {
                uint32_t a = kb + (uint32_t)nbp * (16 * AROWB) + (uint32_t)ks * 32 + offBs;
                LDSM4(kf[nbp*4+0], kf[nbp*4+1], kf[nbp*4+2], kf[nbp*4+3], a + OKH);
                LDSM4(lf[nbp*4+0], lf[nbp*4+1], lf[nbp*4+2], lf[nbp*4+3], a + OKL);
            }
            #pragma unroll
            for (int nbp = 0; nbp < 4; nbp++) {
                MMA_BF16(s[2*nbp],   qh[ks], kf[nbp*4+0], kf[nbp*4+1]);
                MMA_BF16(s[2*nbp+1], qh[ks], kf[nbp*4+2], kf[nbp*4+3]);
            }
            #pragma unroll
            for (int nbp = 0; nbp < 4; nbp++) {
                MMA_BF16(s[2*nbp],   qh[ks], lf[nbp*4+0], lf[nbp*4+1]);
                MMA_BF16(s[2*nbp+1], qh[ks], lf[nbp*4+2], lf[nbp*4+3]);
            }
            #pragma unroll
            for (int nbp = 0; nbp < 4; nbp++) {
                MMA_BF16(s[2*nbp],   ql[ks], kf[nbp*4+0], kf[nbp*4+1]);
                MMA_BF16(s[2*nbp+1], ql[ks], kf[nbp*4+2], kf[nbp*4+3]);
            }
        }

        // ---- online softmax (log2 domain) ----
        float mn0 = s[0][0], mn1 = s[0][2];
        #pragma unroll
        for (int nb = 0; nb < 8; nb++) {
            mn0 = fmaxf(mn0, fmaxf(s[nb][0], s[nb][1]));
            mn1 = fmaxf(mn1, fmaxf(s[nb][2], s[nb][3]));
        }
        mn0 = fmaxf(mn0, __shfl_xor_sync(0xffffffffu, mn0, 1));
        mn0 = fmaxf(mn0, __shfl_xor_sync(0xffffffffu, mn0, 2));
        mn1 = fmaxf(mn1, __shfl_xor_sync(0xffffffffu, mn1, 1));
        mn1 = fmaxf(mn1, __shfl_xor_sync(0xffffffffu, mn1, 2));
        float nm0 = fmaxf(m0, mn0), nm1 = fmaxf(m1, mn1);
        float c0 = ex2f(m0 - nm0), c1 = ex2f(m1 - nm1);
        m0 = nm0; m1 = nm1;

        float sum0 = 0.0f, sum1 = 0.0f;
        #pragma unroll
        for (int nb = 0; nb < 8; nb++) {
            s[nb][0] = ex2f(s[nb][0] - m0);
            s[nb][1] = ex2f(s[nb][1] - m0);
            s[nb][2] = ex2f(s[nb][2] - m1);
            s[nb][3] = ex2f(s[nb][3] - m1);
            sum0 += s[nb][0] + s[nb][1];
            sum1 += s[nb][2] + s[nb][3];
        }
        sum0 += __shfl_xor_sync(0xffffffffu, sum0, 1);
        sum0 += __shfl_xor_sync(0xffffffffu, sum0, 2);
        sum1 += __shfl_xor_sync(0xffffffffu, sum1, 1);
        sum1 += __shfl_xor_sync(0xffffffffu, sum1, 2);
        l0 = l0 * c0 + sum0;
        l1 = l1 * c1 + sum1;
        #pragma unroll
        for (int db = 0; db < 8; db++) {
            ctx[db][0] *= c0; ctx[db][1] *= c0;
            ctx[db][2] *= c1; ctx[db][3] *= c1;
        }

        // ---- ctx += P . V  (per-ks P split + product-outer ordering) ----
        #pragma unroll
        for (int ks = 0; ks < 4; ks++) {
            uint32_t ph[4], pl[4];
            const int e = 2 * ks, o = 2 * ks + 1;
            psplit2(s[e][0], s[e][1], ph[0], pl[0]);
            psplit2(s[e][2], s[e][3], ph[1], pl[1]);
            psplit2(s[o][0], s[o][1], ph[2], pl[2]);
            psplit2(s[o][2], s[o][3], ph[3], pl[3]);

            uint32_t vf[16], wf[16];
            #pragma unroll
            for (int dbp = 0; dbp < 4; dbp++) {
                uint32_t a = kb + (uint32_t)ks * (16 * AROWB) + (uint32_t)dbp * 32 + offBt;
                LDSM4T(vf[dbp*4+0], vf[dbp*4+1], vf[dbp*4+2], vf[dbp*4+3], a + OVH);
                LDSM4T(wf[dbp*4+0], wf[dbp*4+1], wf[dbp*4+2], wf[dbp*4+3], a + OVL);
            }
            #pragma unroll
            for (int dbp = 0; dbp < 4; dbp++) {
                MMA_BF16(ctx[2*dbp],   ph, vf[dbp*4+0], vf[dbp*4+1]);
                MMA_BF16(ctx[2*dbp+1], ph, vf[dbp*4+2], vf[dbp*4+3]);
            }
            #pragma unroll
            for (int dbp = 0; dbp < 4; dbp++) {
                MMA_BF16(ctx[2*dbp],   ph, wf[dbp*4+0], wf[dbp*4+1]);
                MMA_BF16(ctx[2*dbp+1], ph, wf[dbp*4+2], wf[dbp*4+3]);
            }
            #pragma unroll
            for (int dbp = 0; dbp < 4; dbp++) {
                MMA_BF16(ctx[2*dbp],   pl, vf[dbp*4+0], vf[dbp*4+1]);
                MMA_BF16(ctx[2*dbp+1], pl, vf[dbp*4+2], vf[dbp*4+3]);
            }
        }
        // no trailing barrier: next iteration's single barrier covers hazards
    }

    // ---- epilogue: ctx (fp32) + merged split planes ----
    const float i0 = 1.0f / l0, i1 = 1.0f / l1;
    const int r0 = q0 + wid * 16 + (lane >> 2);
    #pragma unroll
    for (int db = 0; db < 8; db++) {
        const int col = db * 8 + (lane & 3) * 2;
        float2 o0, o1;
        o0.x = ctx[db][0] * i0; o0.y = ctx[db][1] * i0;
        o1.x = ctx[db][2] * i1; o1.y = ctx[db][3] * i1;
        *(float2*)&ctx_out[(((size_t)b * NH + h) * NS + r0) * NHD + col]     = o0;
        *(float2*)&ctx_out[(((size_t)b * NH + h) * NS + r0 + 8) * NHD + col] = o1;
        uint32_t hi, lo;
        psplit2(o0.x, o0.y, hi, lo);
        *(uint32_t*)&g_Mh[((size_t)b * NS + r0) * ND + h * NHD + col] = hi;
        *(uint32_t*)&g_Ml[((size_t)b * NS + r0) * ND + h * NHD + col] = lo;
        psplit2(o1.x, o1.y, hi, lo);
        *(uint32_t*)&g_Mh[((size_t)b * NS + r0 + 8) * ND + h * NHD + col] = hi;
        *(uint32_t*)&g_Ml[((size_t)b * NS + r0 + 8) * ND + h * NHD + col] = lo;
    }
}

// ----------------------------------------------------------------------------
extern "C" void kernel_launch(void* const* d_in, const int* in_sizes, int n_in,
                              void* d_out, int out_size)
{
    (void)in_sizes; (void)n_in; (void)out_size;
    const float* q    = (const float*)d_in[0];
    const float* k    = (const float*)d_in[1];
    const float* v    = (const float*)d_in[2];
    const float* wq_w = (const float*)d_in[3];
    const float* wq_b = (const float*)d_in[4];
    const float* wk_w = (const float*)d_in[5];
    const float* wk_b = (const float*)d_in[6];
    const float* wv_w = (const float*)d_in[7];
    const float* wv_b = (const float*)d_in[8];
    const float* wo_w = (const float*)d_in[9];
    const float* wo_b = (const float*)d_in[10];

    float* out = (float*)d_out;                    // [B,S,D]
    float* ctx = out + (size_t)NM * ND;            // [B,H,S,HD]

    cudaFuncSetAttribute(gemm_qkv, cudaFuncAttributeMaxDynamicSharedMemorySize,
                         GSMEM_TOTAL);
    cudaFuncSetAttribute(gemm_o, cudaFuncAttributeMaxDynamicSharedMemorySize,
                         GSMEM_TOTAL);
    cudaFuncSetAttribute(attn_tc, cudaFuncAttributeMaxDynamicSharedMemorySize,
                         ASMEM_TOTAL);

    split_inputs<<<(unsigned)(3 * (A8M >> 2) / 256), 256>>>(q, k, v);
    split_weights<<<(unsigned)(4 * (W1M >> 2) / 256), 256>>>(wq_w, wk_w, wv_w, wo_w);

    dim3 gqkv(ND / 128, NM / 128, 3);              // (8, 64, 3)
    gemm_qkv<<<gqkv, 256, GSMEM_TOTAL>>>(wq_b, wk_b, wv_b);   // -> Q/K/V planes

    attn_tc<<<dim3(NB * NH, NS / 128), 256, ASMEM_TOTAL>>>(ctx); // -> ctx + merged

    dim3 go(ND / 128, NM / 128);                   // (8, 64)
    gemm_o<<<go, 256, GSMEM_TOTAL>>>(wo_b, out);   // -> out
}